// round 12
// baseline (speedup 1.0000x reference)
#include <cuda_runtime.h>
#include <cuda_fp16.h>

#define BINS 10
#define GRID_BLOCKS 444          // 3 CTAs x 148 SMs, persistent single wave
#define BLOCK_THREADS 256

// Device-global scratch (no allocations allowed). Zero at module load;
// the in-kernel finalizer resets after every launch (graph-replay safe).
__device__ double       g_sum[BINS];   // cumulative: sum over bins >= k
__device__ unsigned int g_cnt[BINS];   // cumulative counts
__device__ unsigned int g_ticket;

__device__ __forceinline__ __half2 h2c(unsigned short bits) {
    __half h = __ushort_as_half(bits);
    return __halves2half2(h, h);
}

// f32 front end per element. Log2 domain: q2 = p*(1-2t)*log2e.
//   |sigmoid(p)-t| = sigmoid(q),  bin >= k <=> q2 >= log2(k/(10-k))
//   bce = softplus(q) = (q2 + log2(1+2^q2)) * ln2
// Invalid (w==0) elements get q2 = -1000 so every bin mask is false.
__device__ __forceinline__ void ghmc_elem(float p, float t, float w,
                                          float& q2m, float& bw) {
    const float L2E = 1.44269504089f;
    float sgnl = fmaf(-2.0f * L2E, t, L2E);   // (1-2t)*log2e
    float q2   = p * sgnl;
    q2m = (w > 0.0f) ? q2 : -1000.0f;
    float e2 = exp2f(q2);                     // MUFU.EX2, no pre-scale
    float l  = __log2f(1.0f + e2);            // FADD + MUFU.LG2
    bw = (q2 + l) * 0.69314718056f;           // softplus in natural units
}

// Pairwise half2 cumulative scatter: per threshold one compare-mask,
// one HFMA2 (sum += mask*bce), one HADD2 (count += mask).
__device__ __forceinline__ void ghmc_acc(__half2 qh, __half2 bh,
                                         __half2* hs, __half2* hc,
                                         const __half2* th) {
#pragma unroll
    for (int k = 0; k < BINS; k++) {
        __half2 m = __hge2(qh, th[k]);        // 1.0 / 0.0 per half
        hs[k] = __hfma2(m, bh, hs[k]);
        hc[k] = __hadd2(hc[k], m);
    }
}

__device__ __forceinline__ void ghmc_quad(const float4& p, const float4& t,
                                          const float4& w,
                                          __half2* hs, __half2* hc,
                                          const __half2* th) {
    float qa, qb, ba, bb;
    ghmc_elem(p.x, t.x, w.x, qa, ba);
    ghmc_elem(p.y, t.y, w.y, qb, bb);
    ghmc_acc(__floats2half2_rn(qa, qb), __floats2half2_rn(ba, bb), hs, hc, th);
    ghmc_elem(p.z, t.z, w.z, qa, ba);
    ghmc_elem(p.w, t.w, w.w, qb, bb);
    ghmc_acc(__floats2half2_rn(qa, qb), __floats2half2_rn(ba, bb), hs, hc, th);
}

__global__ void __launch_bounds__(BLOCK_THREADS, 3)
ghmc_kernel(const float4* __restrict__ pred,
            const float4* __restrict__ targ,
            const float4* __restrict__ lw,
            float* __restrict__ out,
            int n4, int n_total) {
    // Thresholds in half (bit-exact):
    // [-100 sentinel(validity), log2(1/9), -2, log2(3/7), log2(4/6), 0,
    //  log2(6/4), log2(7/3), 2, log2(9)]
    const __half2 th[BINS] = {
        h2c(0xD640u), h2c(0xC257u), h2c(0xC000u), h2c(0xBCE4u), h2c(0xB8AEu),
        h2c(0x0000u), h2c(0x38AEu), h2c(0x3CE4u), h2c(0x4000u), h2c(0x4257u)
    };

    __half2 hs[BINS], hc[BINS];
    const __half2 hzero = __halves2half2(__ushort_as_half(0), __ushort_as_half(0));
#pragma unroll
    for (int b = 0; b < BINS; b++) { hs[b] = hzero; hc[b] = hzero; }

    const int gid    = blockIdx.x * BLOCK_THREADS + threadIdx.x;
    const int stride = gridDim.x * BLOCK_THREADS;

    // 2x unrolled grid-stride loop: all SIX float4 loads issued before any
    // processing -> MLP_p1 ~ 6 (double the in-flight DRAM requests).
    int i = gid;
    for (; i + stride < n4; i += 2 * stride) {
        int j = i + stride;
        float4 p0 = pred[i];
        float4 t0 = targ[i];
        float4 w0 = lw[i];
        float4 p1 = pred[j];
        float4 t1 = targ[j];
        float4 w1 = lw[j];
        ghmc_quad(p0, t0, w0, hs, hc, th);
        ghmc_quad(p1, t1, w1, hs, hc, th);
    }
    if (i < n4) {
        float4 p0 = pred[i];
        float4 t0 = targ[i];
        float4 w0 = lw[i];
        ghmc_quad(p0, t0, w0, hs, hc, th);
    }

    // Scalar tail (n_total % 4): one thread, second slot invalidated.
    if (gid == 0) {
        const float* pf = (const float*)pred;
        const float* tf = (const float*)targ;
        const float* wf = (const float*)lw;
        for (int k = n4 * 4; k < n_total; k++) {
            float qa, ba;
            ghmc_elem(pf[k], tf[k], wf[k], qa, ba);
            ghmc_acc(__floats2half2_rn(qa, -1000.0f),
                     __floats2half2_rn(ba, 0.0f), hs, hc, th);
        }
    }

    // Unpack half2 accumulators to f32 (counts <= ~190: exact in half).
    float s[BINS], c[BINS];
#pragma unroll
    for (int b = 0; b < BINS; b++) {
        float2 sf = __half22float2(hs[b]);
        float2 cf = __half22float2(hc[b]);
        s[b] = sf.x + sf.y;
        c[b] = cf.x + cf.y;
    }

    // Warp butterfly reduce (block counts <= 48k: exact in f32).
#pragma unroll
    for (int b = 0; b < BINS; b++)
#pragma unroll
        for (int off = 16; off > 0; off >>= 1) {
            s[b] += __shfl_xor_sync(0xffffffffu, s[b], off);
            c[b] += __shfl_xor_sync(0xffffffffu, c[b], off);
        }

    __shared__ float s_sum[BINS];
    __shared__ float s_cnt[BINS];
    if (threadIdx.x < BINS) { s_sum[threadIdx.x] = 0.0f; s_cnt[threadIdx.x] = 0.0f; }
    __syncthreads();

    if ((threadIdx.x & 31) == 0) {
#pragma unroll
        for (int b = 0; b < BINS; b++) {
            atomicAdd(&s_sum[b], s[b]);
            atomicAdd(&s_cnt[b], c[b]);
        }
    }
    __syncthreads();

    if (threadIdx.x < BINS) {
        atomicAdd(&g_sum[threadIdx.x], (double)s_sum[threadIdx.x]);
        atomicAdd(&g_cnt[threadIdx.x], (unsigned int)(s_cnt[threadIdx.x] + 0.5f));
    }
    __threadfence();
    __syncthreads();

    // Last block: cumulative -> per-bin, compute loss, reset globals.
    if (threadIdx.x == 0) {
        unsigned int done = atomicAdd(&g_ticket, 1u);
        if (done == gridDim.x - 1) {
            __threadfence();
            double loss = 0.0;
            int n = 0;
#pragma unroll
            for (int b = 0; b < BINS; b++) {
                double       sHi = (b < BINS - 1) ? g_sum[b + 1] : 0.0;
                unsigned int cHi = (b < BINS - 1) ? g_cnt[b + 1] : 0u;
                double       Sb  = g_sum[b] - sHi;
                unsigned int Cb  = g_cnt[b] - cHi;
                if (Cb > 0u) { n++; loss += Sb / (double)Cb; }
            }
            out[0] = (n > 0) ? (float)(loss / (double)n) : 0.0f;
#pragma unroll
            for (int b = 0; b < BINS; b++) { g_sum[b] = 0.0; g_cnt[b] = 0u; }
            g_ticket = 0u;
        }
    }
}

extern "C" void kernel_launch(void* const* d_in, const int* in_sizes, int n_in,
                              void* d_out, int out_size) {
    const float4* pred = (const float4*)d_in[0];
    const float4* targ = (const float4*)d_in[1];
    const float4* lw   = (const float4*)d_in[2];
    float* out = (float*)d_out;

    int n_total = in_sizes[0];
    int n4 = n_total / 4;

    ghmc_kernel<<<GRID_BLOCKS, BLOCK_THREADS>>>(pred, targ, lw, out, n4, n_total);
}